// round 5
// baseline (speedup 1.0000x reference)
#include <cuda_runtime.h>
#include <math_constants.h>

// Problem constants
#define NB 32
#define NP 576
#define ND 768
#define KP1 17
#define KF 16
#define NC 200
#define TILE_P 32
#define NTILES 18     // 576 / 32
#define T1 256
#define NDV 192       // ulonglong2 (4 floats) per 768-float row

// Output layout: concatenation of (A, v_norm, logits_parts, logits_agg)
#define SZ_A (NB*KP1*NP)            // 313344
#define OFF_VN (SZ_A)
#define SZ_VN (NB*KF*ND)            // 393216
#define OFF_PARTS (OFF_VN + SZ_VN)
#define SZ_PARTS (NB*KF*NC)         // 102400
#define OFF_AGG (OFF_PARTS + SZ_PARTS)

typedef unsigned long long u64;

// v accumulator (pre-LN). Zeroed at module load; k2a re-zeroes after reading,
// so the "g_v == 0 on k1 entry" invariant holds across graph replays.
__device__ float g_v[NB*KF*ND];

// ---- f32x2 packed-FMA helpers ----------------------------------------------
__device__ __forceinline__ u64 fma2(u64 a, u64 b, u64 c) {
    u64 d; asm("fma.rn.f32x2 %0, %1, %2, %3;" : "=l"(d) : "l"(a), "l"(b), "l"(c));
    return d;
}
__device__ __forceinline__ u64 pack2(float lo, float hi) {
    u64 r; asm("mov.b64 %0, {%1,%2};" : "=l"(r) : "f"(lo), "f"(hi));
    return r;
}
__device__ __forceinline__ float2 unpack2(u64 v) {
    float2 r; asm("mov.b64 {%0,%1}, %2;" : "=f"(r.x), "=f"(r.y) : "l"(v));
    return r;
}

// ---------------------------------------------------------------------------
// k1 phase-1 helper: packed dot products for prototypes [K0, K0+KN).
// Each warp owns 4 patches. Reduction: 3 shfl levels -> 4 partials, stored by
// lanes 0-3; softmax finishes the sum (saves 2 shfl levels per dot).
// ---------------------------------------------------------------------------
template<int K0, int KN>
__device__ __forceinline__ void dot_pass(const ulonglong2* __restrict__ xs2,
                                         const float* __restrict__ proto,
                                         float* a_part, int warp, int lane)
{
    const int p0 = warp * 4;
    u64 acc[4][KN];
    #pragma unroll
    for (int p = 0; p < 4; p++)
        #pragma unroll
        for (int k = 0; k < KN; k++) acc[p][k] = 0ULL;

    const ulonglong2* pr2 = (const ulonglong2*)proto;
    #pragma unroll
    for (int j = 0; j < 6; j++) {
        ulonglong2 xv[4];
        #pragma unroll
        for (int p = 0; p < 4; p++) xv[p] = xs2[(p0 + p)*NDV + j*32 + lane];
        #pragma unroll
        for (int k = 0; k < KN; k++) {
            ulonglong2 pv = __ldg(&pr2[(K0 + k)*NDV + j*32 + lane]);
            #pragma unroll
            for (int p = 0; p < 4; p++) {
                acc[p][k] = fma2(xv[p].x, pv.x, acc[p][k]);
                acc[p][k] = fma2(xv[p].y, pv.y, acc[p][k]);
            }
        }
    }
    #pragma unroll
    for (int p = 0; p < 4; p++)
        #pragma unroll
        for (int k = 0; k < KN; k++) {
            float2 h = unpack2(acc[p][k]);
            float v = h.x + h.y;
            v += __shfl_xor_sync(0xffffffffu, v, 16);
            v += __shfl_xor_sync(0xffffffffu, v, 8);
            v += __shfl_xor_sync(0xffffffffu, v, 4);
            // lane r in {0..3} now holds the partial over lanes ≡ r (mod 4)
            if (lane < 4) a_part[((p0 + p)*KP1 + K0 + k)*4 + lane] = v;
        }
}

// ---------------------------------------------------------------------------
// k1: per (image, 32-patch tile) block. 256 threads, 2 blocks/SM.
//  Stage x + per-block psq -> packed dots -> softmax -> A out, a_s/a_c smem
//  Phase 2: k-major packed fma2 (5 LDS.128 per patch), scalar REDG epilogue.
// ---------------------------------------------------------------------------
__global__ __launch_bounds__(T1, 2)
void k1(const float* __restrict__ x,
        const float* __restrict__ proto,
        float* __restrict__ out)
{
    extern __shared__ float sm[];
    float* xs     = sm;                            // 32*768 floats (96 KB)
    float* a_part = xs + TILE_P*ND;                // 32*17*4 partials (8.5 KB)
    float* a_s    = a_part + TILE_P*KP1*4;         // 32*17 raw a (for A writer)
    float* a_c    = a_s + TILE_P*KP1;              // 32*16 compact a (phase 2)
    float* psq_s  = a_c + TILE_P*KF;               // 17

    const int t = threadIdx.x, warp = t >> 5, lane = t & 31;
    const int b = blockIdx.y, tile = blockIdx.x;

    // --- stage x tile (float4, coalesced) ---
    float4* xs4 = (float4*)xs;
    const float4* xg = (const float4*)(x + ((size_t)b*NP + (size_t)tile*TILE_P)*ND);
    #pragma unroll
    for (int i = 0; i < (TILE_P*ND/4)/T1; i++)     // 24 iters
        xs4[t + i*T1] = xg[t + i*T1];

    // --- per-block ||p_k||^2 (proto L2-resident, overlaps the staging) ---
    for (int k = warp; k < KP1; k += 8) {          // warp0: 0,8,16
        const float4* pk = (const float4*)(proto + (size_t)k*ND);
        float s = 0.f;
        #pragma unroll
        for (int i = 0; i < 6; i++) {
            float4 v = __ldg(&pk[lane + 32*i]);
            s += v.x*v.x + v.y*v.y + v.z*v.z + v.w*v.w;
        }
        #pragma unroll
        for (int o = 16; o; o >>= 1) s += __shfl_xor_sync(0xffffffffu, s, o);
        if (lane == 0) psq_s[k] = s;
    }
    __syncthreads();

    // --- Phase 1: dots, k-split to bound register pressure ---
    const ulonglong2* xs2 = (const ulonglong2*)xs;
    dot_pass<0, 6>(xs2, proto, a_part, warp, lane);
    dot_pass<6, 6>(xs2, proto, a_part, warp, lane);
    dot_pass<12, 5>(xs2, proto, a_part, warp, lane);
    __syncwarp();

    // --- lane-parallel softmax: softmax_k(2*xp - psq) == softmax(-dists) ---
    const int p0 = warp * 4;
    const float4* a_part4 = (const float4*)a_part;
    #pragma unroll
    for (int p = 0; p < 4; p++) {
        const int pl = p0 + p;
        float s = -CUDART_INF_F;
        if (lane < KP1) {
            float4 t4 = a_part4[pl*KP1 + lane];
            float dot = (t4.x + t4.y) + (t4.z + t4.w);
            s = fmaf(2.f, dot, -psq_s[lane]);
        }
        float m = s;
        #pragma unroll
        for (int o = 16; o; o >>= 1) m = fmaxf(m, __shfl_xor_sync(0xffffffffu, m, o));
        float e = (lane < KP1) ? __expf(s - m) : 0.f;
        float ssum = e;
        #pragma unroll
        for (int o = 16; o; o >>= 1) ssum += __shfl_xor_sync(0xffffffffu, ssum, o);
        float av = e * (1.f / ssum);
        if (lane < KP1) {
            a_s[pl*KP1 + lane] = av;
            if (lane < KF) a_c[pl*KF + lane] = av;
        }
    }
    __syncthreads();

    if (t >= 192) {
        // --- A output, coalesced 128B rows, on otherwise-idle threads ---
        int tt = t - 192;
        #pragma unroll
        for (int i = tt; i < KP1*TILE_P; i += 64) {
            int k = i >> 5, p = i & 31;
            out[((size_t)b*KP1 + k)*NP + (size_t)tile*TILE_P + p] = a_s[p*KP1 + k];
        }
    } else {
        // --- Phase 2: 192 threads each own a d-quad; k-major packed fma2 ---
        // acc[kp][d] packs (v[2kp][d], v[2kp+1][d]); a-pairs load with zero movs.
        u64 vacc[8][4];
        #pragma unroll
        for (int kp = 0; kp < 8; kp++)
            #pragma unroll
            for (int d = 0; d < 4; d++) vacc[kp][d] = 0ULL;

        #pragma unroll 4
        for (int p = 0; p < TILE_P; p++) {
            float4 xv = xs4[p*NDV + t];
            u64 xd[4] = { pack2(xv.x, xv.x), pack2(xv.y, xv.y),
                          pack2(xv.z, xv.z), pack2(xv.w, xv.w) };
            const ulonglong2* ac2 = (const ulonglong2*)(a_c + p*KF);
            ulonglong2 A0 = ac2[0], A1 = ac2[1], A2 = ac2[2], A3 = ac2[3];
            u64 ap[8] = { A0.x, A0.y, A1.x, A1.y, A2.x, A2.y, A3.x, A3.y };
            #pragma unroll
            for (int kp = 0; kp < 8; kp++)
                #pragma unroll
                for (int d = 0; d < 4; d++)
                    vacc[kp][d] = fma2(ap[kp], xd[d], vacc[kp][d]);
        }
        float* gv = g_v + (size_t)b*KF*ND;
        #pragma unroll
        for (int kp = 0; kp < 8; kp++)
            #pragma unroll
            for (int d = 0; d < 4; d++) {
                float2 h = unpack2(vacc[kp][d]);
                atomicAdd(&gv[(size_t)(2*kp    )*ND + 4*t + d], h.x);
                atomicAdd(&gv[(size_t)(2*kp + 1)*ND + 4*t + d], h.y);
            }
    }
}

// ---------------------------------------------------------------------------
// k2a: LayerNorm over D for each (b,k). Applies the /P scaling.
// Also: re-zeroes g_v (read-then-clear) and seeds parts/agg with the bias so
// k2b can use pure atomics and no init kernel is needed.
// ---------------------------------------------------------------------------
__global__ __launch_bounds__(256, 4)
void k2a(float* __restrict__ out,
         const float* __restrict__ gamma, const float* __restrict__ beta,
         const float* __restrict__ b_cls)
{
    const int bk = blockIdx.x;            // b*16 + k
    const int t = threadIdx.x;
    __shared__ float red[16];
    __shared__ float stats[2];
    float* gv = g_v + (size_t)bk*ND;
    const float invP = 1.f / (float)NP;

    float v[3]; float s = 0.f, sq = 0.f;
    #pragma unroll
    for (int i = 0; i < 3; i++) {
        float val = gv[t + i*256] * invP;
        gv[t + i*256] = 0.f;              // re-zero for next replay's k1
        v[i] = val; s += val; sq += val*val;
    }

    // seed logits_parts / logits_agg with the classifier bias
    if (t < NC) {
        float bcv = b_cls[t];
        out[OFF_PARTS + (size_t)bk*NC + t] = bcv;
        if ((bk & 15) == 0) out[OFF_AGG + (size_t)(bk >> 4)*NC + t] = bcv;
    }

    #pragma unroll
    for (int o = 16; o; o >>= 1) {
        s  += __shfl_xor_sync(0xffffffffu, s, o);
        sq += __shfl_xor_sync(0xffffffffu, sq, o);
    }
    if ((t & 31) == 0) { red[t >> 5] = s; red[8 + (t >> 5)] = sq; }
    __syncthreads();
    if (t == 0) {
        float S = 0.f, Q = 0.f;
        #pragma unroll
        for (int w = 0; w < 8; w++) { S += red[w]; Q += red[8 + w]; }
        float mu  = S * (1.f/ND);
        float var = Q * (1.f/ND) - mu*mu;
        stats[0] = mu; stats[1] = rsqrtf(var + 1e-6f);
    }
    __syncthreads();
    const float mu = stats[0], rs = stats[1];
    #pragma unroll
    for (int i = 0; i < 3; i++) {
        int d = t + i*256;
        out[OFF_VN + (size_t)bk*ND + d] = (v[i] - mu) * rs * gamma[d] + beta[d];
    }
}

// ---------------------------------------------------------------------------
// k2b: logits_parts[b,k,c] += vn[b,k,dchunk] @ w[dchunk,c]; agg folded in.
// 16 d-chunks of 48 per image -> 512 blocks; unroll-8 for MLP; w L2-resident.
// Bias pre-seeded by k2a, so pure red.global.add.
// ---------------------------------------------------------------------------
#define DCH 48
__global__ __launch_bounds__(256, 4)
void k2b(const float* __restrict__ w, float* __restrict__ out)
{
    const int dc = blockIdx.x;            // 0..15
    const int b  = blockIdx.y;
    const int t  = threadIdx.x;
    __shared__ u64 vn_s[KF*(DCH/2)];      // packed d-pairs (3 KB)

    const float* vn = out + OFF_VN + (size_t)b*KF*ND + dc*DCH;
    for (int i = t; i < KF*(DCH/2); i += 256) {
        int k = i / (DCH/2), dp = i - k*(DCH/2);
        float2 v = *(const float2*)&vn[(size_t)k*ND + 2*dp];
        vn_s[i] = pack2(v.x, v.y);
    }
    __syncthreads();

    if (t < NC) {
        const float* wp = w + (size_t)(dc*DCH)*NC + t;   // coalesced in c
        u64 acc[KF];
        #pragma unroll
        for (int k = 0; k < KF; k++) acc[k] = 0ULL;
        #pragma unroll 8
        for (int dp = 0; dp < DCH/2; dp++) {
            float w0 = __ldg(wp + (size_t)(2*dp)*NC);
            float w1 = __ldg(wp + (size_t)(2*dp + 1)*NC);
            u64 wv = pack2(w0, w1);
            #pragma unroll
            for (int k = 0; k < KF; k++)
                acc[k] = fma2(vn_s[k*(DCH/2) + dp], wv, acc[k]);
        }
        float* parts = out + OFF_PARTS + (size_t)b*KF*NC + t;
        float ssum = 0.f;
        #pragma unroll
        for (int k = 0; k < KF; k++) {
            float2 h = unpack2(acc[k]);
            float s = h.x + h.y;
            atomicAdd(parts + (size_t)k*NC, s);
            ssum += s;
        }
        atomicAdd(out + OFF_AGG + b*NC + t, ssum * (1.f/KF));
    }
}

// ---------------------------------------------------------------------------
extern "C" void kernel_launch(void* const* d_in, const int* in_sizes, int n_in,
                              void* d_out, int out_size)
{
    const float* x     = (const float*)d_in[0];  // (32,24,24,768)
    const float* proto = (const float*)d_in[1];  // (17,768)
    const float* gamma = (const float*)d_in[2];  // (768,)
    const float* beta  = (const float*)d_in[3];  // (768,)
    const float* w     = (const float*)d_in[4];  // (768,200)
    const float* bc    = (const float*)d_in[5];  // (200,)
    float* out = (float*)d_out;

    const size_t smem1 = (size_t)(TILE_P*ND            // xs
                                + TILE_P*KP1*4         // a_part
                                + TILE_P*KP1           // a_s
                                + TILE_P*KF            // a_c
                                + KP1) * sizeof(float);  // ~107 KB
    cudaFuncSetAttribute(k1, cudaFuncAttributeMaxDynamicSharedMemorySize, (int)smem1);

    k1<<<dim3(NTILES, NB), T1, smem1>>>(x, proto, out);
    k2a<<<NB*KF, 256>>>(out, gamma, beta, bc);
    k2b<<<dim3(16, NB), 256>>>(w, out);
}